// round 14
// baseline (speedup 1.0000x reference)
#include <cuda_runtime.h>
#include <cstdint>

// B=4, C=80, M=16 fixed by the reference; N derived at runtime (76725 @640x640).
#define BB 4
#define CC 80
#define C4 20            // float4 per anchor row
#define MM 16
#define TILE 512         // anchors per block (two per thread in phase 1)
#define THREADS 256

#define IMG_W 640.0f
#define IMG_H 640.0f
#define EPS_F 1e-4f
#define BETA_F (1.0f / 9.0f)
#define LN2_F 0.6931471805599453f

__device__ float        g_cls_sum[BB];
__device__ float        g_reg_sum[BB];
__device__ int          g_pos[BB];
__device__ unsigned int g_count = 0;

// Packed focal-negative step for an element pair (x,y): acc2 += p^2 * lg2(1-p).
__device__ __forceinline__ void foc2(float x, float y,
                                     unsigned long long& acc2,
                                     unsigned long long nones,   // {-1,-1}
                                     unsigned long long ones) {  // { 1, 1}
    unsigned long long v2, u2, l2, sq2;
    asm("mov.b64 %0, {%1, %2};" : "=l"(v2) : "f"(x), "f"(y));
    asm("fma.rn.f32x2 %0, %1, %2, %3;" : "=l"(u2) : "l"(v2), "l"(nones), "l"(ones));
    float ulo, uhi, llo, lhi;
    asm("mov.b64 {%0, %1}, %2;" : "=f"(ulo), "=f"(uhi) : "l"(u2));
    asm("lg2.approx.f32 %0, %1;" : "=f"(llo) : "f"(ulo));
    asm("lg2.approx.f32 %0, %1;" : "=f"(lhi) : "f"(uhi));
    asm("mov.b64 %0, {%1, %2};" : "=l"(l2) : "f"(llo), "f"(lhi));
    asm("mul.rn.f32x2 %0, %1, %2;" : "=l"(sq2) : "l"(v2), "l"(v2));
    asm("fma.rn.f32x2 %0, %1, %2, %3;" : "=l"(acc2) : "l"(sq2), "l"(l2), "l"(acc2));
}

__device__ __forceinline__ void cpasync16(uint32_t dst, const float4* __restrict__ src) {
    asm volatile("cp.async.cg.shared.global [%0], [%1], 16;" :: "r"(dst), "l"(src));
}
#define CP_COMMIT()  asm volatile("cp.async.commit_group;" ::: "memory")
#define CP_WAIT(n)   asm volatile("cp.async.wait_group %0;" :: "n"(n) : "memory")

// Per-anchor assignment: label, smooth-L1 contribution, positive focal correction.
__device__ __forceinline__ float assign_one(
    long img, int n, int N, float4 a4, int sanyv,
    const float4* __restrict__ sbox, const float2* __restrict__ sthr,
    const float* __restrict__ scls,
    const float* __restrict__ cls, const float* __restrict__ regs,
    float& my_reg, float& my_pos, float& my_cor) {

    const float a0 = a4.x, a1 = a4.y, a2 = a4.z, a3 = a4.w;
    const bool inside = (a0 > 0.0f) && (a1 > 0.0f) && (a2 < IMG_W) && (a3 < IMG_H);
    const float area_a = (a2 - a0) * (a3 - a1);
    const float t04 = 0.4f * area_a;
    const float t05 = 0.5f * area_a;

    float m04 = -1e30f, m05 = -1e30f;
#pragma unroll
    for (int j = 0; j < MM; j++) {
        const float4 g  = sbox[j];
        const float2 th = sthr[j];
        const float lx = fmaxf(a0, g.x), ly = fmaxf(a1, g.y);
        const float rx = fminf(a2, g.z), ry = fminf(a3, g.w);
        const float wx = fmaxf(rx - lx, 0.0f), wy = fmaxf(ry - ly, 0.0f);
        const float num = wx * wy;
        m04 = fmaxf(m04, fmaf(num, 1.4f, -th.x));
        m05 = fmaxf(m05, fmaf(num, 1.5f, -th.y));
    }

    float label = (m04 < t04) ? 0.0f : -1.0f;
    const bool is_pos = (m05 > t05) && sanyv && inside && (n < N);
    if (!sanyv || !inside || n >= N) label = -1.0f;

    if (is_pos) {
        // rare path: exact argmax with the original tie ordering
        const long an = img + n;
        float cn = -1.0f, cd = 1.0f;
        int bidx = 0;
#pragma unroll
        for (int j = 0; j < MM; j++) {
            const float4 g = sbox[j];
            const float area_g = sthr[j].x * 2.5f;
            const float lx = fmaxf(a0, g.x), ly = fmaxf(a1, g.y);
            const float rx = fminf(a2, g.z), ry = fminf(a3, g.w);
            const float wx = fmaxf(rx - lx, 0.0f), wy = fmaxf(ry - ly, 0.0f);
            const float num = wx * wy;
            const float den = area_a + area_g - num;
            if (num * cd > cn * den) { cn = num; cd = den; bidx = j; }
        }
        label = scls[bidx] + 1.0f;

        const float4 g = sbox[bidx];
        const float aw = a2 - a0, ah = a3 - a1;
        const float acx = a0 + 0.5f * aw, acy = a1 + 0.5f * ah;
        const float gw = fmaxf(g.z - g.x, 1.0f);
        const float gh = fmaxf(g.w - g.y, 1.0f);
        const float gcx = g.x + 0.5f * gw, gcy = g.y + 0.5f * gh;
        const float t0 = ((gcx - acx) / aw) * 10.0f;
        const float t1 = ((gcy - acy) / ah) * 10.0f;
        const float t2 = __logf(gw / aw) * 5.0f;
        const float t3 = __logf(gh / ah) * 5.0f;

        const float4 r4 = reinterpret_cast<const float4*>(regs)[an];
        const float xs[4] = { fabsf(r4.x - t0), fabsf(r4.y - t1),
                              fabsf(r4.z - t2), fabsf(r4.w - t3) };
#pragma unroll
        for (int k = 0; k < 4; k++) {
            const float x = xs[k];
            my_reg += (x < BETA_F) ? (0.5f * x * x / BETA_F) : (x - 0.5f * BETA_F);
        }
        my_pos += 1.0f;

        const int lp = (int)label - 1;
        const float pv = cls[an * CC + lp];
        const float p = fminf(fmaxf(pv, EPS_F), 1.0f - EPS_F);
        const float q = 1.0f - p;
        my_cor += 0.25f * q * q * (-__logf(p)) - 0.75f * pv * pv * (-__logf(1.0f - pv));
    }
    return label;
}

__global__ void __launch_bounds__(THREADS, 4)
retina_fused_kernel(const float* __restrict__ cls,
                    const float* __restrict__ regs,
                    const float* __restrict__ anchors,
                    const float* __restrict__ annots,
                    float* __restrict__ out,
                    int N) {
    const int b    = blockIdx.y;
    const int n0   = blockIdx.x * TILE;
    const int tid  = threadIdx.x;
    const int lane = tid & 31;
    const int wrp  = tid >> 5;
    const long img = (long)b * N;

    __shared__ float4 sbuf[2][5][THREADS];   // 2 x 20KB ping-pong staging
    __shared__ float4 sbox[MM];
    __shared__ float2 sthr[MM];              // {0.4*area_g, 0.5*area_g}
    __shared__ float  scls[MM];
    __shared__ int    sanyv;
    __shared__ float  swred[8][3];

    uint32_t sdst[2];
    sdst[0] = (uint32_t)__cvta_generic_to_shared(&sbuf[0][0][tid]);
    sdst[1] = (uint32_t)__cvta_generic_to_shared(&sbuf[1][0][tid]);
    const uint32_t srow = THREADS * 16;

    // ---- Phase 0: warp-local geometry + chunk-0 cp.async before any math ----
    const int ag = lane >> 2;                 // anchor subgroup 0..7 within warp
    const int abase = n0 + wrp * 64;          // warp's first anchor (64 per warp)
    const float4* __restrict__ cf4 = reinterpret_cast<const float4*>(cls);
    // chunk k covers anchors abase + 8k + ag, k = 0..7
    const float4* p[8];
#pragma unroll
    for (int k = 0; k < 8; k++)
        p[k] = cf4 + (img + min(abase + 8 * k + ag, N - 1)) * C4 + (lane & 3);

#pragma unroll
    for (int it = 0; it < 5; it++) cpasync16(sdst[0] + it * srow, p[0] + it * 4);
    CP_COMMIT();   // group c0 -> buf0

    // this thread's two anchors (warp-local mapping)
    const int nL = abase + lane;              // first 32 of warp's anchors
    const int nH = abase + 32 + lane;         // second 32
    const float4 a4L = reinterpret_cast<const float4*>(anchors)[img + min(nL, N - 1)];
    const float4 a4H = reinterpret_cast<const float4*>(anchors)[img + min(nH, N - 1)];

    // GT preprocessing (zero invalid boxes -> their IoU is 0, can never win)
    if (tid < MM) {
        const float* g = annots + (b * MM + tid) * 5;
        float g0 = g[0], g1 = g[1], g2 = g[2], g3 = g[3], gc = g[4];
        const bool valid = (gc >= 0.0f);
        const unsigned bal = __ballot_sync(0x0000ffffu, valid);
        if (tid == 0) sanyv = (bal != 0u);
        if (!valid) { g0 = g1 = g2 = g3 = 0.0f; gc = 0.0f; }
        sbox[tid] = make_float4(g0, g1, g2, g3);
        const float ag2 = (g2 - g0) * (g3 - g1);
        sthr[tid] = make_float2(0.4f * ag2, 0.5f * ag2);
        scls[tid] = gc;
    }
    __syncthreads();   // the only barrier before the final reduction

    // ---- Phase 1: two anchors per thread, overlapped with chunk-0 cp.async ----
    float my_reg = 0.0f, my_pos = 0.0f, my_cor = 0.0f;
    const float labL = assign_one(img, nL, N, a4L, sanyv, sbox, sthr, scls,
                                  cls, regs, my_reg, my_pos, my_cor);
    const float labH = assign_one(img, nH, N, a4H, sanyv, sbox, sthr, scls,
                                  cls, regs, my_reg, my_pos, my_cor);

    // ---- Label gates for the 8 chunks (warp-local shuffles) ----
    bool u[8];
#pragma unroll
    for (int k = 0; k < 4; k++)
        u[k] = (__shfl_sync(0xffffffffu, labL, k * 8 + ag) >= 0.0f);
#pragma unroll
    for (int k = 4; k < 8; k++)
        u[k] = (__shfl_sync(0xffffffffu, labH, (k - 4) * 8 + ag) >= 0.0f);

    unsigned long long ones, nones, acc2;
    {
        const float one = 1.0f, mone = -1.0f, zero = 0.0f;
        asm("mov.b64 %0, {%1, %1};" : "=l"(ones)  : "f"(one));
        asm("mov.b64 %0, {%1, %1};" : "=l"(nones) : "f"(mone));
        asm("mov.b64 %0, {%1, %1};" : "=l"(acc2)  : "f"(zero));
    }

    // ---- Phase 2: 8-chunk cp.async ping-pong (issue k+1 ahead, wait, math) ----
    if (u[1]) {
#pragma unroll
        for (int it = 0; it < 5; it++) cpasync16(sdst[1] + it * srow, p[1] + it * 4);
    }
    CP_COMMIT();   // pending {c0, c1}

#pragma unroll
    for (int k = 0; k < 8; k++) {
        if (k < 6) CP_WAIT(1); else if (k == 6) CP_WAIT(1); else CP_WAIT(0);
        if (u[k]) {
            float4 v[5];
#pragma unroll
            for (int it = 0; it < 5; it++) v[it] = sbuf[k & 1][it][tid];
#pragma unroll
            for (int it = 0; it < 5; it++) {
                foc2(v[it].x, v[it].y, acc2, nones, ones);
                foc2(v[it].z, v[it].w, acc2, nones, ones);
            }
        }
        if (k < 6) {
            if (u[k + 2]) {
#pragma unroll
                for (int it = 0; it < 5; it++)
                    cpasync16(sdst[k & 1] + it * srow, p[k + 2] + it * 4);
            }
            CP_COMMIT();
        }
    }

    float slo, shi;
    asm("mov.b64 {%0, %1}, %2;" : "=f"(slo), "=f"(shi) : "l"(acc2));
    float acc = fmaf(-0.75f * LN2_F, slo + shi, my_cor);

    // ---- Phase 3: warp shuffle reduce, one barrier, 3 atomics per block ----
#pragma unroll
    for (int o = 16; o; o >>= 1) {
        acc    += __shfl_down_sync(0xffffffffu, acc,    o);
        my_reg += __shfl_down_sync(0xffffffffu, my_reg, o);
        my_pos += __shfl_down_sync(0xffffffffu, my_pos, o);
    }
    if (lane == 0) {
        swred[wrp][0] = acc;
        swred[wrp][1] = my_reg;
        swred[wrp][2] = my_pos;
    }
    __syncthreads();
    if (tid == 0) {
        float c = 0.0f, r = 0.0f, pz = 0.0f;
#pragma unroll
        for (int w = 0; w < 8; w++) {
            c += swred[w][0];
            r += swred[w][1];
            pz += swred[w][2];
        }
        if (c != 0.0f) atomicAdd(&g_cls_sum[b], c);
        if (r != 0.0f) atomicAdd(&g_reg_sum[b], r);
        const int pi = (int)(pz + 0.5f);
        if (pi) atomicAdd(&g_pos[b], pi);
    }

    // ---- Phase 4: last block finalizes + resets state for next replay ----
    __shared__ bool is_last;
    __threadfence();
    if (tid == 0) {
        const unsigned total = gridDim.x * gridDim.y;
        is_last = (atomicAdd(&g_count, 1u) == total - 1u);
    }
    __syncthreads();
    if (!is_last) return;

    if (tid == 0) {
        float cls_l = 0.0f, reg_l = 0.0f, nvalid = 0.0f;
#pragma unroll
        for (int bi = 0; bi < BB; bi++) {
            const float pz = (float)g_pos[bi];
            if (pz > 0.0f) {
                cls_l += g_cls_sum[bi] / pz;
                reg_l += g_reg_sum[bi] / (4.0f * pz);
                nvalid += 1.0f;
            }
            g_cls_sum[bi] = 0.0f;
            g_reg_sum[bi] = 0.0f;
            g_pos[bi] = 0;
        }
        nvalid = fmaxf(nvalid, 1.0f);
        out[0] = cls_l / nvalid;
        out[1] = reg_l / nvalid;
        g_count = 0;
    }
}

extern "C" void kernel_launch(void* const* d_in, const int* in_sizes, int n_in,
                              void* d_out, int out_size) {
    const float* cls     = (const float*)d_in[0];  // (B, N, C)
    const float* regs    = (const float*)d_in[1];  // (B, N, 4)
    const float* anchors = (const float*)d_in[2];  // (B, N, 4)
    const float* annots  = (const float*)d_in[3];  // (B, M, 5)

    const int N = in_sizes[1] / (BB * 4);
    const int numTiles = (N + TILE - 1) / TILE;   // 150 @ N=76725

    dim3 grid(numTiles, BB);                      // 600 blocks ~= one wave
    retina_fused_kernel<<<grid, THREADS>>>(cls, regs, anchors, annots,
                                           (float*)d_out, N);
}

// round 15
// speedup vs baseline: 1.5710x; 1.5710x over previous
#include <cuda_runtime.h>
#include <cstdint>

// B=4, C=80, M=16 fixed by the reference; N derived at runtime (76725 @640x640).
#define BB 4
#define CC 80
#define C4 20            // float4 per anchor row
#define MM 16
#define TILE 256         // anchors per block (one per thread in phase 1)
#define THREADS 256

#define IMG_W 640.0f
#define IMG_H 640.0f
#define EPS_F 1e-4f
#define BETA_F (1.0f / 9.0f)
#define LN2_F 0.6931471805599453f

__device__ float        g_cls_sum[BB];
__device__ float        g_reg_sum[BB];
__device__ int          g_pos[BB];
__device__ unsigned int g_count = 0;

// Packed focal-negative step for an element pair (x,y): acc2 += p^2 * lg2(1-p).
__device__ __forceinline__ void foc2(float x, float y,
                                     unsigned long long& acc2,
                                     unsigned long long nones,   // {-1,-1}
                                     unsigned long long ones) {  // { 1, 1}
    unsigned long long v2, u2, l2, sq2;
    asm("mov.b64 %0, {%1, %2};" : "=l"(v2) : "f"(x), "f"(y));
    asm("fma.rn.f32x2 %0, %1, %2, %3;" : "=l"(u2) : "l"(v2), "l"(nones), "l"(ones));
    float ulo, uhi, llo, lhi;
    asm("mov.b64 {%0, %1}, %2;" : "=f"(ulo), "=f"(uhi) : "l"(u2));
    asm("lg2.approx.f32 %0, %1;" : "=f"(llo) : "f"(ulo));
    asm("lg2.approx.f32 %0, %1;" : "=f"(lhi) : "f"(uhi));
    asm("mov.b64 %0, {%1, %2};" : "=l"(l2) : "f"(llo), "f"(lhi));
    asm("mul.rn.f32x2 %0, %1, %2;" : "=l"(sq2) : "l"(v2), "l"(v2));
    asm("fma.rn.f32x2 %0, %1, %2, %3;" : "=l"(acc2) : "l"(sq2), "l"(l2), "l"(acc2));
}

__device__ __forceinline__ void cpasync16(uint32_t dst, const float4* __restrict__ src) {
    asm volatile("cp.async.cg.shared.global [%0], [%1], 16;" :: "r"(dst), "l"(src));
}
#define CP_COMMIT()  asm volatile("cp.async.commit_group;" ::: "memory")
#define CP_WAIT(n)   asm volatile("cp.async.wait_group %0;" :: "n"(n) : "memory")

__global__ void __launch_bounds__(THREADS, 4)
retina_fused_kernel(const float* __restrict__ cls,
                    const float* __restrict__ regs,
                    const float* __restrict__ anchors,
                    const float* __restrict__ annots,
                    float* __restrict__ out,
                    int N) {
    const int b    = blockIdx.y;
    const int n0   = blockIdx.x * TILE;
    const int tid  = threadIdx.x;
    const int lane = tid & 31;
    const int wrp  = tid >> 5;
    const long img = (long)b * N;

    __shared__ float4 sbuf[2][5][THREADS];   // 2 x 20KB ping-pong staging
    __shared__ float4 sbox[MM];
    __shared__ float2 sthr[MM];              // {0.4*area_g, 0.5*area_g}
    __shared__ float  scls[MM];
    __shared__ int    sanyv;
    __shared__ float  swred[8][3];

    uint32_t sdst[2];
    sdst[0] = (uint32_t)__cvta_generic_to_shared(&sbuf[0][0][tid]);
    sdst[1] = (uint32_t)__cvta_generic_to_shared(&sbuf[1][0][tid]);
    const uint32_t srow = THREADS * 16;      // bytes between [it] slices

    // ---- Phase 0: cp.async chunks A and B (both ungated) before any math ----
    const int ag = lane >> 2;                 // anchor group 0..7 within warp
    const int abase = n0 + wrp * 32;          // warp's first anchor
    const float4* __restrict__ cf4 = reinterpret_cast<const float4*>(cls);
    const float4* __restrict__ pA = cf4 + (img + min(abase + ag,      N - 1)) * C4 + (lane & 3);
    const float4* __restrict__ pB = cf4 + (img + min(abase + ag + 8,  N - 1)) * C4 + (lane & 3);
    const float4* __restrict__ pC = cf4 + (img + min(abase + ag + 16, N - 1)) * C4 + (lane & 3);
    const float4* __restrict__ pD = cf4 + (img + min(abase + ag + 24, N - 1)) * C4 + (lane & 3);

#pragma unroll
    for (int it = 0; it < 5; it++) cpasync16(sdst[0] + it * srow, pA + it * 4);
    CP_COMMIT();   // group: A -> buf0
#pragma unroll
    for (int it = 0; it < 5; it++) cpasync16(sdst[1] + it * srow, pB + it * 4);
    CP_COMMIT();   // group: B -> buf1   (10 LDGSTS in flight through phase 1)

    const int n = n0 + tid;
    const float4 a4 = reinterpret_cast<const float4*>(anchors)[img + min(n, N - 1)];

    // GT preprocessing (zero invalid boxes -> their IoU is 0, can never win)
    if (tid < MM) {
        const float* g = annots + (b * MM + tid) * 5;
        float g0 = g[0], g1 = g[1], g2 = g[2], g3 = g[3], gc = g[4];
        const bool valid = (gc >= 0.0f);
        const unsigned bal = __ballot_sync(0x0000ffffu, valid);
        if (tid == 0) sanyv = (bal != 0u);
        if (!valid) { g0 = g1 = g2 = g3 = 0.0f; gc = 0.0f; }
        sbox[tid] = make_float4(g0, g1, g2, g3);
        const float ag2 = (g2 - g0) * (g3 - g1);
        sthr[tid] = make_float2(0.4f * ag2, 0.5f * ag2);
        scls[tid] = gc;
    }
    __syncthreads();   // the only barrier before the final reduction

    // ---- Phase 1 (one anchor per thread): overlapped with A+B cp.async ----
    float label  = -1.0f;
    float my_reg = 0.0f;
    float my_pos = 0.0f;
    float my_cor = 0.0f;
    {
        const float a0 = a4.x, a1 = a4.y, a2 = a4.z, a3 = a4.w;
        const bool inside = (a0 > 0.0f) && (a1 > 0.0f) && (a2 < IMG_W) && (a3 < IMG_H);
        const float area_a = (a2 - a0) * (a3 - a1);
        const float t04 = 0.4f * area_a;
        const float t05 = 0.5f * area_a;

        float m04 = -1e30f, m05 = -1e30f;
#pragma unroll
        for (int j = 0; j < MM; j++) {
            const float4 g  = sbox[j];
            const float2 th = sthr[j];
            const float lx = fmaxf(a0, g.x), ly = fmaxf(a1, g.y);
            const float rx = fminf(a2, g.z), ry = fminf(a3, g.w);
            const float wx = fmaxf(rx - lx, 0.0f), wy = fmaxf(ry - ly, 0.0f);
            const float num = wx * wy;
            m04 = fmaxf(m04, fmaf(num, 1.4f, -th.x));
            m05 = fmaxf(m05, fmaf(num, 1.5f, -th.y));
        }

        label = (m04 < t04) ? 0.0f : -1.0f;
        const bool is_pos = (m05 > t05) && sanyv && inside && (n < N);
        if (!sanyv || !inside || n >= N) label = -1.0f;

        if (is_pos) {
            // rare path: exact argmax with the original tie ordering
            const long an = img + n;
            float cn = -1.0f, cd = 1.0f;
            int bidx = 0;
#pragma unroll
            for (int j = 0; j < MM; j++) {
                const float4 g = sbox[j];
                const float area_g = sthr[j].x * 2.5f;
                const float lx = fmaxf(a0, g.x), ly = fmaxf(a1, g.y);
                const float rx = fminf(a2, g.z), ry = fminf(a3, g.w);
                const float wx = fmaxf(rx - lx, 0.0f), wy = fmaxf(ry - ly, 0.0f);
                const float num = wx * wy;
                const float den = area_a + area_g - num;
                if (num * cd > cn * den) { cn = num; cd = den; bidx = j; }
            }
            label = scls[bidx] + 1.0f;

            const float4 g = sbox[bidx];
            const float aw = a2 - a0, ah = a3 - a1;
            const float acx = a0 + 0.5f * aw, acy = a1 + 0.5f * ah;
            const float gw = fmaxf(g.z - g.x, 1.0f);
            const float gh = fmaxf(g.w - g.y, 1.0f);
            const float gcx = g.x + 0.5f * gw, gcy = g.y + 0.5f * gh;
            const float t0 = ((gcx - acx) / aw) * 10.0f;
            const float t1 = ((gcy - acy) / ah) * 10.0f;
            const float t2 = __logf(gw / aw) * 5.0f;
            const float t3 = __logf(gh / ah) * 5.0f;

            const float4 r4 = reinterpret_cast<const float4*>(regs)[an];
            const float xs[4] = { fabsf(r4.x - t0), fabsf(r4.y - t1),
                                  fabsf(r4.z - t2), fabsf(r4.w - t3) };
#pragma unroll
            for (int k = 0; k < 4; k++) {
                const float x = xs[k];
                my_reg += (x < BETA_F) ? (0.5f * x * x / BETA_F) : (x - 0.5f * BETA_F);
            }
            my_pos = 1.0f;

            const int lp = (int)label - 1;
            const float pv = cls[an * CC + lp];
            const float p = fminf(fmaxf(pv, EPS_F), 1.0f - EPS_F);
            const float q = 1.0f - p;
            my_cor = 0.25f * q * q * (-__logf(p)) - 0.75f * pv * pv * (-__logf(1.0f - pv));
        }
    }

    // ---- Label exchange within the warp (no block barrier) ----
    const bool uA = (__shfl_sync(0xffffffffu, label, ag)      >= 0.0f);
    const bool uB = (__shfl_sync(0xffffffffu, label, ag + 8)  >= 0.0f);
    const bool uC = (__shfl_sync(0xffffffffu, label, ag + 16) >= 0.0f);
    const bool uD = (__shfl_sync(0xffffffffu, label, ag + 24) >= 0.0f);

    unsigned long long ones, nones, acc2;
    {
        const float one = 1.0f, mone = -1.0f, zero = 0.0f;
        asm("mov.b64 %0, {%1, %1};" : "=l"(ones)  : "f"(one));
        asm("mov.b64 %0, {%1, %1};" : "=l"(nones) : "f"(mone));
        asm("mov.b64 %0, {%1, %1};" : "=l"(acc2)  : "f"(zero));
    }

    // ---- Phase 2: ping-pong; every math interval has a load in flight ----
    CP_WAIT(1);                  // A complete (B may still be in flight)
    if (uA) {
        float4 v[5];
#pragma unroll
        for (int it = 0; it < 5; it++) v[it] = sbuf[0][it][tid];
#pragma unroll
        for (int it = 0; it < 5; it++) {
            foc2(v[it].x, v[it].y, acc2, nones, ones);
            foc2(v[it].z, v[it].w, acc2, nones, ones);
        }
    }
    // issue C -> buf0 (A's math done reading it)
    if (uC) {
#pragma unroll
        for (int it = 0; it < 5; it++) cpasync16(sdst[0] + it * srow, pC + it * 4);
    }
    CP_COMMIT();                 // pending: {B, C}

    CP_WAIT(1);                  // B complete
    if (uB) {
        float4 v[5];
#pragma unroll
        for (int it = 0; it < 5; it++) v[it] = sbuf[1][it][tid];
#pragma unroll
        for (int it = 0; it < 5; it++) {
            foc2(v[it].x, v[it].y, acc2, nones, ones);
            foc2(v[it].z, v[it].w, acc2, nones, ones);
        }
    }
    // issue D -> buf1
    if (uD) {
#pragma unroll
        for (int it = 0; it < 5; it++) cpasync16(sdst[1] + it * srow, pD + it * 4);
    }
    CP_COMMIT();                 // pending: {C, D}

    CP_WAIT(1);                  // C complete
    if (uC) {
        float4 v[5];
#pragma unroll
        for (int it = 0; it < 5; it++) v[it] = sbuf[0][it][tid];
#pragma unroll
        for (int it = 0; it < 5; it++) {
            foc2(v[it].x, v[it].y, acc2, nones, ones);
            foc2(v[it].z, v[it].w, acc2, nones, ones);
        }
    }
    CP_WAIT(0);                  // D complete
    if (uD) {
        float4 v[5];
#pragma unroll
        for (int it = 0; it < 5; it++) v[it] = sbuf[1][it][tid];
#pragma unroll
        for (int it = 0; it < 5; it++) {
            foc2(v[it].x, v[it].y, acc2, nones, ones);
            foc2(v[it].z, v[it].w, acc2, nones, ones);
        }
    }

    float slo, shi;
    asm("mov.b64 {%0, %1}, %2;" : "=f"(slo), "=f"(shi) : "l"(acc2));
    float acc = fmaf(-0.75f * LN2_F, slo + shi, my_cor);

    // ---- Phase 3: warp shuffle reduce, one barrier, 3 atomics per block ----
#pragma unroll
    for (int o = 16; o; o >>= 1) {
        acc    += __shfl_down_sync(0xffffffffu, acc,    o);
        my_reg += __shfl_down_sync(0xffffffffu, my_reg, o);
        my_pos += __shfl_down_sync(0xffffffffu, my_pos, o);
    }
    if (lane == 0) {
        swred[wrp][0] = acc;
        swred[wrp][1] = my_reg;
        swred[wrp][2] = my_pos;
    }
    __syncthreads();
    if (tid == 0) {
        float c = 0.0f, r = 0.0f, p = 0.0f;
#pragma unroll
        for (int w = 0; w < 8; w++) {
            c += swred[w][0];
            r += swred[w][1];
            p += swred[w][2];
        }
        if (c != 0.0f) atomicAdd(&g_cls_sum[b], c);
        if (r != 0.0f) atomicAdd(&g_reg_sum[b], r);
        const int pi = (int)(p + 0.5f);
        if (pi) atomicAdd(&g_pos[b], pi);
    }

    // ---- Phase 4: last block finalizes + resets state for next replay ----
    __shared__ bool is_last;
    __threadfence();
    if (tid == 0) {
        const unsigned total = gridDim.x * gridDim.y;
        is_last = (atomicAdd(&g_count, 1u) == total - 1u);
    }
    __syncthreads();
    if (!is_last) return;

    if (tid == 0) {
        float cls_l = 0.0f, reg_l = 0.0f, nvalid = 0.0f;
#pragma unroll
        for (int bi = 0; bi < BB; bi++) {
            const float p = (float)g_pos[bi];
            if (p > 0.0f) {
                cls_l += g_cls_sum[bi] / p;
                reg_l += g_reg_sum[bi] / (4.0f * p);
                nvalid += 1.0f;
            }
            g_cls_sum[bi] = 0.0f;
            g_reg_sum[bi] = 0.0f;
            g_pos[bi] = 0;
        }
        nvalid = fmaxf(nvalid, 1.0f);
        out[0] = cls_l / nvalid;
        out[1] = reg_l / nvalid;
        g_count = 0;
    }
}

extern "C" void kernel_launch(void* const* d_in, const int* in_sizes, int n_in,
                              void* d_out, int out_size) {
    const float* cls     = (const float*)d_in[0];  // (B, N, C)
    const float* regs    = (const float*)d_in[1];  // (B, N, 4)
    const float* anchors = (const float*)d_in[2];  // (B, N, 4)
    const float* annots  = (const float*)d_in[3];  // (B, M, 5)

    const int N = in_sizes[1] / (BB * 4);
    const int numTiles = (N + TILE - 1) / TILE;

    dim3 grid(numTiles, BB);
    retina_fused_kernel<<<grid, THREADS>>>(cls, regs, anchors, annots,
                                           (float*)d_out, N);
}

// round 16
// speedup vs baseline: 1.5854x; 1.0091x over previous
#include <cuda_runtime.h>
#include <cstdint>

// B=4, C=80, M=16 fixed by the reference; N derived at runtime (76725 @640x640).
#define BB 4
#define CC 80
#define C4 20            // float4 per anchor row
#define MM 16
#define TILE 256         // anchors per block (one per thread in phase 1)
#define THREADS 256

#define IMG_W 640.0f
#define IMG_H 640.0f
#define EPS_F 1e-4f
#define BETA_F (1.0f / 9.0f)
#define LN2_F 0.6931471805599453f

__device__ float        g_cls_sum[BB];
__device__ float        g_reg_sum[BB];
__device__ int          g_pos[BB];
__device__ unsigned int g_count = 0;

// Packed focal-negative step for an element pair (x,y): acc2 += p^2 * lg2(1-p).
__device__ __forceinline__ void foc2(float x, float y,
                                     unsigned long long& acc2,
                                     unsigned long long nones,   // {-1,-1}
                                     unsigned long long ones) {  // { 1, 1}
    unsigned long long v2, u2, l2, sq2;
    asm("mov.b64 %0, {%1, %2};" : "=l"(v2) : "f"(x), "f"(y));
    asm("fma.rn.f32x2 %0, %1, %2, %3;" : "=l"(u2) : "l"(v2), "l"(nones), "l"(ones));
    float ulo, uhi, llo, lhi;
    asm("mov.b64 {%0, %1}, %2;" : "=f"(ulo), "=f"(uhi) : "l"(u2));
    asm("lg2.approx.f32 %0, %1;" : "=f"(llo) : "f"(ulo));
    asm("lg2.approx.f32 %0, %1;" : "=f"(lhi) : "f"(uhi));
    asm("mov.b64 %0, {%1, %2};" : "=l"(l2) : "f"(llo), "f"(lhi));
    asm("mul.rn.f32x2 %0, %1, %2;" : "=l"(sq2) : "l"(v2), "l"(v2));
    asm("fma.rn.f32x2 %0, %1, %2, %3;" : "=l"(acc2) : "l"(sq2), "l"(l2), "l"(acc2));
}

__device__ __forceinline__ void cpasync16(uint32_t dst, const float4* __restrict__ src) {
    asm volatile("cp.async.cg.shared.global [%0], [%1], 16;" :: "r"(dst), "l"(src));
}
#define CP_COMMIT()  asm volatile("cp.async.commit_group;" ::: "memory")
#define CP_WAIT(n)   asm volatile("cp.async.wait_group %0;" :: "n"(n) : "memory")

__device__ __forceinline__ float unpack_sum(unsigned long long a) {
    float lo, hi;
    asm("mov.b64 {%0, %1}, %2;" : "=f"(lo), "=f"(hi) : "l"(a));
    return lo + hi;
}

__global__ void __launch_bounds__(THREADS, 4)
retina_fused_kernel(const float* __restrict__ cls,
                    const float* __restrict__ regs,
                    const float* __restrict__ anchors,
                    const float* __restrict__ annots,
                    float* __restrict__ out,
                    int N) {
    const int b    = blockIdx.y;
    const int n0   = blockIdx.x * TILE;
    const int tid  = threadIdx.x;
    const int lane = tid & 31;
    const int wrp  = tid >> 5;
    const long img = (long)b * N;

    __shared__ float4 sbuf[2][5][THREADS];   // 2 x 20KB ping-pong staging
    __shared__ float4 sbox[MM];
    __shared__ float2 sthr[MM];              // {0.4*area_g, 0.5*area_g}
    __shared__ float  scls[MM];
    __shared__ int    sanyv;
    __shared__ float  swred[8][3];

    uint32_t sdst[2];
    sdst[0] = (uint32_t)__cvta_generic_to_shared(&sbuf[0][0][tid]);
    sdst[1] = (uint32_t)__cvta_generic_to_shared(&sbuf[1][0][tid]);
    const uint32_t srow = THREADS * 16;      // bytes between [it] slices

    // ---- Phase 0: cp.async chunks A and B (ungated) before any math ----
    const int ag = lane >> 2;                 // anchor group 0..7 within warp
    const int abase = n0 + wrp * 32;          // warp's first anchor
    const float4* __restrict__ cf4 = reinterpret_cast<const float4*>(cls);
    const float4* __restrict__ pA = cf4 + (img + min(abase + ag,      N - 1)) * C4 + (lane & 3);
    const float4* __restrict__ pB = cf4 + (img + min(abase + ag + 8,  N - 1)) * C4 + (lane & 3);
    const float4* __restrict__ pC = cf4 + (img + min(abase + ag + 16, N - 1)) * C4 + (lane & 3);
    const float4* __restrict__ pD = cf4 + (img + min(abase + ag + 24, N - 1)) * C4 + (lane & 3);

#pragma unroll
    for (int it = 0; it < 5; it++) cpasync16(sdst[0] + it * srow, pA + it * 4);
    CP_COMMIT();   // group: A -> buf0
#pragma unroll
    for (int it = 0; it < 5; it++) cpasync16(sdst[1] + it * srow, pB + it * 4);
    CP_COMMIT();   // group: B -> buf1

    const int n = n0 + tid;
    const float4 a4 = reinterpret_cast<const float4*>(anchors)[img + min(n, N - 1)];

    // GT preprocessing (zero invalid boxes -> their IoU is 0, can never win)
    if (tid < MM) {
        const float* g = annots + (b * MM + tid) * 5;
        float g0 = g[0], g1 = g[1], g2 = g[2], g3 = g[3], gc = g[4];
        const bool valid = (gc >= 0.0f);
        const unsigned bal = __ballot_sync(0x0000ffffu, valid);
        if (tid == 0) sanyv = (bal != 0u);
        if (!valid) { g0 = g1 = g2 = g3 = 0.0f; gc = 0.0f; }
        sbox[tid] = make_float4(g0, g1, g2, g3);
        const float ag2 = (g2 - g0) * (g3 - g1);
        sthr[tid] = make_float2(0.4f * ag2, 0.5f * ag2);
        scls[tid] = gc;
    }
    __syncthreads();

    // ---- Early inside gates (depend only on the anchor box; one ballot) ----
    const bool inside = (a4.x > 0.0f) && (a4.y > 0.0f) && (a4.z < IMG_W) && (a4.w < IMG_H);
    const unsigned ibal = __ballot_sync(0xffffffffu, inside);
    const bool iA = (ibal >> ag)        & 1u;
    const bool iB = (ibal >> (ag + 8))  & 1u;
    const bool iC = (ibal >> (ag + 16)) & 1u;
    const bool iD = (ibal >> (ag + 24)) & 1u;

    unsigned long long ones, nones, sA, sB, sCD;
    {
        const float one = 1.0f, mone = -1.0f, zero = 0.0f;
        asm("mov.b64 %0, {%1, %1};" : "=l"(ones)  : "f"(one));
        asm("mov.b64 %0, {%1, %1};" : "=l"(nones) : "f"(mone));
        asm("mov.b64 %0, {%1, %1};" : "=l"(sA)    : "f"(zero));
        sB = sA; sCD = sA;
    }

    // ---- mathA / issue C / mathB / issue D  (inside-gated; labels not needed) ----
    CP_WAIT(1);                  // A complete
    if (iA) {
        float4 v[5];
#pragma unroll
        for (int it = 0; it < 5; it++) v[it] = sbuf[0][it][tid];
#pragma unroll
        for (int it = 0; it < 5; it++) {
            foc2(v[it].x, v[it].y, sA, nones, ones);
            foc2(v[it].z, v[it].w, sA, nones, ones);
        }
    }
    if (iC) {
#pragma unroll
        for (int it = 0; it < 5; it++) cpasync16(sdst[0] + it * srow, pC + it * 4);
    }
    CP_COMMIT();                 // pending: {B, C}

    CP_WAIT(1);                  // B complete
    if (iB) {
        float4 v[5];
#pragma unroll
        for (int it = 0; it < 5; it++) v[it] = sbuf[1][it][tid];
#pragma unroll
        for (int it = 0; it < 5; it++) {
            foc2(v[it].x, v[it].y, sB, nones, ones);
            foc2(v[it].z, v[it].w, sB, nones, ones);
        }
    }
    if (iD) {
#pragma unroll
        for (int it = 0; it < 5; it++) cpasync16(sdst[1] + it * srow, pD + it * 4);
    }
    CP_COMMIT();                 // pending: {C, D}

    // ---- Phase 1 (covers C and D flight time): labels + reg loss + correction ----
    float label  = -1.0f;
    float my_reg = 0.0f;
    float my_pos = 0.0f;
    float my_cor = 0.0f;
    {
        const float a0 = a4.x, a1 = a4.y, a2 = a4.z, a3 = a4.w;
        const float area_a = (a2 - a0) * (a3 - a1);
        const float t04 = 0.4f * area_a;
        const float t05 = 0.5f * area_a;

        float m04 = -1e30f, m05 = -1e30f;
#pragma unroll
        for (int j = 0; j < MM; j++) {
            const float4 g  = sbox[j];
            const float2 th = sthr[j];
            const float lx = fmaxf(a0, g.x), ly = fmaxf(a1, g.y);
            const float rx = fminf(a2, g.z), ry = fminf(a3, g.w);
            const float wx = fmaxf(rx - lx, 0.0f), wy = fmaxf(ry - ly, 0.0f);
            const float num = wx * wy;
            m04 = fmaxf(m04, fmaf(num, 1.4f, -th.x));
            m05 = fmaxf(m05, fmaf(num, 1.5f, -th.y));
        }

        label = (m04 < t04) ? 0.0f : -1.0f;
        const bool is_pos = (m05 > t05) && sanyv && inside && (n < N);
        if (!sanyv || !inside || n >= N) label = -1.0f;

        if (is_pos) {
            // rare path: exact argmax with the original tie ordering
            const long an = img + n;
            float cn = -1.0f, cd = 1.0f;
            int bidx = 0;
#pragma unroll
            for (int j = 0; j < MM; j++) {
                const float4 g = sbox[j];
                const float area_g = sthr[j].x * 2.5f;
                const float lx = fmaxf(a0, g.x), ly = fmaxf(a1, g.y);
                const float rx = fminf(a2, g.z), ry = fminf(a3, g.w);
                const float wx = fmaxf(rx - lx, 0.0f), wy = fmaxf(ry - ly, 0.0f);
                const float num = wx * wy;
                const float den = area_a + area_g - num;
                if (num * cd > cn * den) { cn = num; cd = den; bidx = j; }
            }
            label = scls[bidx] + 1.0f;

            const float4 g = sbox[bidx];
            const float aw = a2 - a0, ah = a3 - a1;
            const float acx = a0 + 0.5f * aw, acy = a1 + 0.5f * ah;
            const float gw = fmaxf(g.z - g.x, 1.0f);
            const float gh = fmaxf(g.w - g.y, 1.0f);
            const float gcx = g.x + 0.5f * gw, gcy = g.y + 0.5f * gh;
            const float t0 = ((gcx - acx) / aw) * 10.0f;
            const float t1 = ((gcy - acy) / ah) * 10.0f;
            const float t2 = __logf(gw / aw) * 5.0f;
            const float t3 = __logf(gh / ah) * 5.0f;

            const float4 r4 = reinterpret_cast<const float4*>(regs)[an];
            const float xs[4] = { fabsf(r4.x - t0), fabsf(r4.y - t1),
                                  fabsf(r4.z - t2), fabsf(r4.w - t3) };
#pragma unroll
            for (int k = 0; k < 4; k++) {
                const float x = xs[k];
                my_reg += (x < BETA_F) ? (0.5f * x * x / BETA_F) : (x - 0.5f * BETA_F);
            }
            my_pos = 1.0f;

            const int lp = (int)label - 1;
            const float pv = cls[an * CC + lp];
            const float p = fminf(fmaxf(pv, EPS_F), 1.0f - EPS_F);
            const float q = 1.0f - p;
            my_cor = 0.25f * q * q * (-__logf(p)) - 0.75f * pv * pv * (-__logf(1.0f - pv));
        }
    }

    // ---- Label gates (one ballot) ----
    const unsigned lbal = __ballot_sync(0xffffffffu, label >= 0.0f);
    const bool uA = (lbal >> ag)        & 1u;
    const bool uB = (lbal >> (ag + 8))  & 1u;
    const bool uC = (lbal >> (ag + 16)) & 1u;
    const bool uD = (lbal >> (ag + 24)) & 1u;

    // ---- mathC / mathD (label+inside gated directly; loads already landed) ----
    CP_WAIT(1);                  // C complete
    if (uC) {
        float4 v[5];
#pragma unroll
        for (int it = 0; it < 5; it++) v[it] = sbuf[0][it][tid];
#pragma unroll
        for (int it = 0; it < 5; it++) {
            foc2(v[it].x, v[it].y, sCD, nones, ones);
            foc2(v[it].z, v[it].w, sCD, nones, ones);
        }
    }
    CP_WAIT(0);                  // D complete
    if (uD) {
        float4 v[5];
#pragma unroll
        for (int it = 0; it < 5; it++) v[it] = sbuf[1][it][tid];
#pragma unroll
        for (int it = 0; it < 5; it++) {
            foc2(v[it].x, v[it].y, sCD, nones, ones);
            foc2(v[it].z, v[it].w, sCD, nones, ones);
        }
    }

    // ---- Combine: post-hoc label gating for A,B; C,D already label-gated ----
    float ssum = unpack_sum(sCD);
    if (uA) ssum += unpack_sum(sA);
    if (uB) ssum += unpack_sum(sB);
    float acc = fmaf(-0.75f * LN2_F, ssum, my_cor);

    // ---- Phase 3: warp shuffle reduce, one barrier, 3 atomics per block ----
#pragma unroll
    for (int o = 16; o; o >>= 1) {
        acc    += __shfl_down_sync(0xffffffffu, acc,    o);
        my_reg += __shfl_down_sync(0xffffffffu, my_reg, o);
        my_pos += __shfl_down_sync(0xffffffffu, my_pos, o);
    }
    if (lane == 0) {
        swred[wrp][0] = acc;
        swred[wrp][1] = my_reg;
        swred[wrp][2] = my_pos;
    }
    __syncthreads();
    if (tid == 0) {
        float c = 0.0f, r = 0.0f, p = 0.0f;
#pragma unroll
        for (int w = 0; w < 8; w++) {
            c += swred[w][0];
            r += swred[w][1];
            p += swred[w][2];
        }
        if (c != 0.0f) atomicAdd(&g_cls_sum[b], c);
        if (r != 0.0f) atomicAdd(&g_reg_sum[b], r);
        const int pi = (int)(p + 0.5f);
        if (pi) atomicAdd(&g_pos[b], pi);
    }

    // ---- Phase 4: last block finalizes + resets state for next replay ----
    __shared__ bool is_last;
    __threadfence();
    if (tid == 0) {
        const unsigned total = gridDim.x * gridDim.y;
        is_last = (atomicAdd(&g_count, 1u) == total - 1u);
    }
    __syncthreads();
    if (!is_last) return;

    if (tid == 0) {
        float cls_l = 0.0f, reg_l = 0.0f, nvalid = 0.0f;
#pragma unroll
        for (int bi = 0; bi < BB; bi++) {
            const float p = (float)g_pos[bi];
            if (p > 0.0f) {
                cls_l += g_cls_sum[bi] / p;
                reg_l += g_reg_sum[bi] / (4.0f * p);
                nvalid += 1.0f;
            }
            g_cls_sum[bi] = 0.0f;
            g_reg_sum[bi] = 0.0f;
            g_pos[bi] = 0;
        }
        nvalid = fmaxf(nvalid, 1.0f);
        out[0] = cls_l / nvalid;
        out[1] = reg_l / nvalid;
        g_count = 0;
    }
}

extern "C" void kernel_launch(void* const* d_in, const int* in_sizes, int n_in,
                              void* d_out, int out_size) {
    const float* cls     = (const float*)d_in[0];  // (B, N, C)
    const float* regs    = (const float*)d_in[1];  // (B, N, 4)
    const float* anchors = (const float*)d_in[2];  // (B, N, 4)
    const float* annots  = (const float*)d_in[3];  // (B, M, 5)

    const int N = in_sizes[1] / (BB * 4);
    const int numTiles = (N + TILE - 1) / TILE;

    dim3 grid(numTiles, BB);
    retina_fused_kernel<<<grid, THREADS>>>(cls, regs, anchors, annots,
                                           (float*)d_out, N);
}